// round 5
// baseline (speedup 1.0000x reference)
#include <cuda_runtime.h>
#include <cuda_bf16.h>
#include <cstdint>

// out[v, t, n] = tlut[encoded[t, n], v]
// tlut:   (65536, 2) float32 -> contiguous float2 (8B) per entry
// encoded:(128, 262144) int32
// out:    (2, 128, 262144) float32
//
// L1tex-wavefront-bound gather. Hybrid LUT, take 2:
//  - 29056 entries (232448 B = smem opt-in max, 44.3% of table) in SMEM
//  - per gather: select shared-vs-global pointer (selp), ONE generic LD
//    -> smem-resident gathers cost conflict-degree (~3) wavefronts per warp
//       instead of ~32, cutting total l1tex wavefronts to ~0.68x
//  - persistent 148 CTAs x 1024 threads, 8 gathers in flight per thread

static constexpr long long TB_ = 128;
static constexpr long long N_  = 262144;
static constexpr long long TOTAL  = TB_ * N_;      // 33,554,432 per plane
static constexpr long long TOTAL4 = TOTAL / 4;     // 8,388,608 quads

static constexpr int SMEM_ENTRIES = 29056;               // float2 entries
static constexpr int SMEM_BYTES   = SMEM_ENTRIES * 8;    // 232448 = opt-in max
static constexpr int NUM_CTAS     = 148;
static constexpr int NUM_THREADS  = 1024;
static constexpr int QUADS_PER_THREAD = 2;

__device__ __forceinline__ const float2* sel_ptr(int e,
                                                 const float2* ls,
                                                 const float2* lg)
{
    // Both addresses computed, pointer selected -> single generic LD.
    return (e < SMEM_ENTRIES) ? (ls + e) : (lg + e);
}

__global__ void __launch_bounds__(NUM_THREADS, 1)
bitshift_lut_hybrid2_kernel(const float2* __restrict__ lut,
                            const int4*  __restrict__ enc,
                            float4* __restrict__ out0,
                            float4* __restrict__ out1)
{
    extern __shared__ float2 lut_s[];

    // One-time fill of the SMEM-resident LUT slice (coalesced).
    #pragma unroll 4
    for (int i = threadIdx.x; i < SMEM_ENTRIES; i += NUM_THREADS)
        lut_s[i] = __ldg(&lut[i]);
    __syncthreads();

    const long long stride = (long long)NUM_CTAS * NUM_THREADS * QUADS_PER_THREAD;

    for (long long base = (long long)blockIdx.x * (NUM_THREADS * QUADS_PER_THREAD)
                          + threadIdx.x;
         base < TOTAL4; base += stride)
    {
        long long base2 = base + NUM_THREADS;
        bool has2 = (base2 < TOTAL4);

        int4 e0 = __ldcg(&enc[base]);
        int4 e1 = has2 ? __ldcg(&enc[base2]) : make_int4(0, 0, 0, 0);

        // 8 independent generic gathers in flight
        float2 a0 = *sel_ptr(e0.x, lut_s, lut);
        float2 b0 = *sel_ptr(e0.y, lut_s, lut);
        float2 c0 = *sel_ptr(e0.z, lut_s, lut);
        float2 d0 = *sel_ptr(e0.w, lut_s, lut);
        float2 a1 = *sel_ptr(e1.x, lut_s, lut);
        float2 b1 = *sel_ptr(e1.y, lut_s, lut);
        float2 c1 = *sel_ptr(e1.z, lut_s, lut);
        float2 d1 = *sel_ptr(e1.w, lut_s, lut);

        out0[base] = make_float4(a0.x, b0.x, c0.x, d0.x);   // plane v=0
        out1[base] = make_float4(a0.y, b0.y, c0.y, d0.y);   // plane v=1
        if (has2) {
            out0[base2] = make_float4(a1.x, b1.x, c1.x, d1.x);
            out1[base2] = make_float4(a1.y, b1.y, c1.y, d1.y);
        }
    }
}

extern "C" void kernel_launch(void* const* d_in, const int* in_sizes, int n_in,
                              void* d_out, int out_size)
{
    const float2* lut = (const float2*)d_in[0];   // tlut (65536, 2)
    const int4*   enc = (const int4*)d_in[1];     // encoded (128, 262144)
    float* out = (float*)d_out;                   // (2, 128, 262144)

    float4* out0 = (float4*)out;
    float4* out1 = (float4*)(out + TOTAL);

    cudaFuncSetAttribute(bitshift_lut_hybrid2_kernel,
                         cudaFuncAttributeMaxDynamicSharedMemorySize, SMEM_BYTES);

    bitshift_lut_hybrid2_kernel<<<NUM_CTAS, NUM_THREADS, SMEM_BYTES>>>(
        lut, enc, out0, out1);
}